// round 3
// baseline (speedup 1.0000x reference)
#include <cuda_runtime.h>
#include <cuda_bf16.h>
#include <stdint.h>

#define NMAX 100000
#define EMAX 1600000
#define D 48
#define NSTEPS 5
#define NGRAPH 64
#define BN_EPS 1e-5f

// ---------------- device scratch (static: allocation-free rule) ----------------
__device__ int   g_is64;
__device__ int   g_deg[NMAX];
__device__ float g_dinv[NMAX];
__device__ int   g_rowstart[NMAX + 1];
__device__ int   g_wp[NMAX];
__device__ int   g_ecol[EMAX];
__device__ int   g_scanblk[256];
__device__ int   g_scanoff[256];
__device__ float g_X [NMAX * D];   // current node features / pool output
__device__ float g_Y [NMAX * D];   // dinv-prescaled features (gather source)
__device__ float g_T1[NMAX * D];   // Tx1
__device__ float g_T2[NMAX * D];   // Tx2
__device__ float g_T [NMAX * D];   // relu(cheb) output
__device__ double g_bnsum[D];
__device__ double g_bnsq[D];
__device__ float g_a[D];
__device__ float g_c[D];
__device__ float g_g[NGRAPH * D];
__device__ int   g_gstart[NGRAPH + 1];

// Read index i from a buffer that is either int64 or int32, per flag.
__device__ __forceinline__ int idx_get(const void* p, int i, int is64) {
    return is64 ? (int)((const long long*)p)[i] : ((const int*)p)[i];
}

// ---------------- dtype detection: is edge_index int64? ----------------
// Reads indices < EE interpreted as int64 — in-bounds under BOTH dtypes
// (EE int64 reads = 8*EE bytes = exactly 2*EE int32 elements).
__global__ void k_detect(const void* ei, int EE, int NN) {
    const long long* p = (const long long*)ei;
    int t = threadIdx.x;
    int stride = EE / 256;
    if (stride < 1) stride = 1;
    int e = t * stride;
    int ok = 1;
    if (e < EE) {
        long long v = p[e];
        if (v < 0 || v >= (long long)NN) ok = 0;
    }
    int all = __syncthreads_and(ok);
    if (t == 0) g_is64 = all;
}

// ---------------- init: copy x, zero deg ----------------
__global__ void k_init(const float* __restrict__ x, int NN) {
    int total = NN * D;
    for (int i = blockIdx.x * blockDim.x + threadIdx.x; i < total;
         i += gridDim.x * blockDim.x) {
        g_X[i] = x[i];
        if (i < NN) g_deg[i] = 0;
    }
}

__global__ void k_count(const void* __restrict__ ei, int EE, int NN) {
    int is64 = g_is64;
    for (int e = blockIdx.x * blockDim.x + threadIdx.x; e < EE;
         e += gridDim.x * blockDim.x) {
        int r = idx_get(ei, e, is64);
        if ((unsigned)r < (unsigned)NN) atomicAdd(&g_deg[r], 1);
    }
}

__global__ void k_dinv(int NN) {
    int i = blockIdx.x * blockDim.x + threadIdx.x;
    if (i < NN) {
        int d = g_deg[i];
        g_dinv[i] = (d > 0) ? rsqrtf((float)d) : 0.0f;
    }
}

// ---------------- 3-kernel exclusive prefix scan over deg ----------------
__global__ void k_scan1(int NN) {
    __shared__ int sh[1024];
    int t = threadIdx.x;
    int i = blockIdx.x * 1024 + t;
    int v = (i < NN) ? g_deg[i] : 0;
    sh[t] = v;
    __syncthreads();
    for (int off = 1; off < 1024; off <<= 1) {
        int tv = (t >= off) ? sh[t - off] : 0;
        __syncthreads();
        sh[t] += tv;
        __syncthreads();
    }
    if (i < NN) g_rowstart[i] = sh[t] - v;   // exclusive, pre-offset
    if (t == 1023) g_scanblk[blockIdx.x] = sh[1023];
}

__global__ void k_scan2(int NB) {
    __shared__ int sh[128];
    int t = threadIdx.x;
    int v = (t < NB) ? g_scanblk[t] : 0;
    sh[t] = v;
    __syncthreads();
    for (int off = 1; off < 128; off <<= 1) {
        int tv = (t >= off) ? sh[t - off] : 0;
        __syncthreads();
        sh[t] += tv;
        __syncthreads();
    }
    g_scanoff[t] = sh[t] - v;  // exclusive block offsets
}

__global__ void k_scan3(int NN, int EE) {
    int i = blockIdx.x * 1024 + threadIdx.x;
    if (i < NN) {
        int rs = g_rowstart[i] + g_scanoff[blockIdx.x];
        g_rowstart[i] = rs;
        g_wp[i] = rs;
    }
    if (i == 0) g_rowstart[NN] = EE;
}

__global__ void k_bucket(const void* __restrict__ ei, int EE, int NN) {
    int is64 = g_is64;
    for (int e = blockIdx.x * blockDim.x + threadIdx.x; e < EE;
         e += gridDim.x * blockDim.x) {
        int r = idx_get(ei, e, is64);
        int c = idx_get(ei, EE + e, is64);
        if ((unsigned)r < (unsigned)NN && (unsigned)c < (unsigned)NN) {
            int p = atomicAdd(&g_wp[r], 1);
            if ((unsigned)p < (unsigned)EMAX) g_ecol[p] = c;
        }
    }
}

// ---------------- prescale: Y = dinv[n] * SRC[n]  (SRC = X or T1) -----------
template <int SRC>
__global__ __launch_bounds__(256) void k_prescale(int NN) {
    int total = NN * D;
    const float* __restrict__ src = (SRC == 0) ? g_X : g_T1;
    for (int i = blockIdx.x * blockDim.x + threadIdx.x; i < total;
         i += gridDim.x * blockDim.x) {
        g_Y[i] = g_dinv[i / D] * src[i];
    }
}

// ---------------- CSR gather kernels ----------------
// MODE 0: T1[row] = -dinv[row] * sum_e Y[c]               (lhat on X, Y=dinv*X)
// MODE 1: T2[row] = -2*dinv[row]* sum_e Y[c] - X[row]     (Y=dinv*T1)
// MODE 2: X[row]  = deg>0 ? max_e (a*T[c]+c) : 0          (BN + seg max pool)
template <int MODE>
__global__ __launch_bounds__(384) void k_gather(int NN) {
    int row = blockIdx.x * 8 + threadIdx.y;
    if (row >= NN) return;
    int f = threadIdx.x;  // 0..47
    int s = g_rowstart[row];
    int e = g_rowstart[row + 1];

    if (MODE == 2) {
        float av = g_a[f], cv = g_c[f];
        float m = __int_as_float(0xff800000);  // -inf
        for (int i = s; i < e; i++) {
            int c = __ldg(&g_ecol[i]);
            m = fmaxf(m, fmaf(av, __ldg(&g_T[c * D + f]), cv));
        }
        g_X[row * D + f] = (e > s) ? m : 0.0f;
    } else {
        float acc = 0.0f;
        for (int i = s; i < e; i++) {
            int c = __ldg(&g_ecol[i]);
            acc += __ldg(&g_Y[c * D + f]);
        }
        if (MODE == 0) {
            g_T1[row * D + f] = -g_dinv[row] * acc;
        } else {
            g_T2[row * D + f] = fmaf(-2.0f * g_dinv[row], acc, -g_X[row * D + f]);
        }
    }
}

// ---------------- fused cheb GEMM: T = relu(X@W0 + T1@W1 + T2@W2 + b) ----------
#define TILE_N 64
#define XS_STRIDE 68

__global__ __launch_bounds__(192) void k_gemm(const float* __restrict__ W,
                                              const float* __restrict__ b,
                                              int NN) {
    __shared__ float xs[144 * XS_STRIDE];
    int tid = threadIdx.x;
    int f_id = tid % 12;
    int n_id = tid / 12;
    int f0 = f_id * 4;
    int n0 = n_id * 4;

    int nodebase = blockIdx.x * TILE_N;

    for (int v = tid; v < 3 * TILE_N * 12; v += 192) {
        int buf = v / (TILE_N * 12);
        int rem = v % (TILE_N * 12);
        int node = rem / 12;
        int c4 = rem % 12;
        const float* sp = (buf == 0) ? g_X : (buf == 1) ? g_T1 : g_T2;
        float4 val = make_float4(0.f, 0.f, 0.f, 0.f);
        int gn = nodebase + node;
        if (gn < NN) val = *(const float4*)(sp + gn * D + c4 * 4);
        int kb = buf * 48 + c4 * 4;
        xs[(kb + 0) * XS_STRIDE + node] = val.x;
        xs[(kb + 1) * XS_STRIDE + node] = val.y;
        xs[(kb + 2) * XS_STRIDE + node] = val.z;
        xs[(kb + 3) * XS_STRIDE + node] = val.w;
    }
    __syncthreads();

    float acc[4][4];
#pragma unroll
    for (int i = 0; i < 4; i++)
#pragma unroll
        for (int j = 0; j < 4; j++) acc[i][j] = 0.0f;

#pragma unroll 4
    for (int k = 0; k < 144; k++) {
        float4 wv = __ldg((const float4*)(W + k * 48 + f0));
        float4 xv = *(const float4*)&xs[k * XS_STRIDE + n0];
        acc[0][0] = fmaf(xv.x, wv.x, acc[0][0]);
        acc[0][1] = fmaf(xv.x, wv.y, acc[0][1]);
        acc[0][2] = fmaf(xv.x, wv.z, acc[0][2]);
        acc[0][3] = fmaf(xv.x, wv.w, acc[0][3]);
        acc[1][0] = fmaf(xv.y, wv.x, acc[1][0]);
        acc[1][1] = fmaf(xv.y, wv.y, acc[1][1]);
        acc[1][2] = fmaf(xv.y, wv.z, acc[1][2]);
        acc[1][3] = fmaf(xv.y, wv.w, acc[1][3]);
        acc[2][0] = fmaf(xv.z, wv.x, acc[2][0]);
        acc[2][1] = fmaf(xv.z, wv.y, acc[2][1]);
        acc[2][2] = fmaf(xv.z, wv.z, acc[2][2]);
        acc[2][3] = fmaf(xv.z, wv.w, acc[2][3]);
        acc[3][0] = fmaf(xv.w, wv.x, acc[3][0]);
        acc[3][1] = fmaf(xv.w, wv.y, acc[3][1]);
        acc[3][2] = fmaf(xv.w, wv.z, acc[3][2]);
        acc[3][3] = fmaf(xv.w, wv.w, acc[3][3]);
    }

    float4 bv = __ldg((const float4*)(b + f0));
#pragma unroll
    for (int i = 0; i < 4; i++) {
        int gn = nodebase + n0 + i;
        if (gn < NN) {
            float4 o;
            o.x = fmaxf(acc[i][0] + bv.x, 0.0f);
            o.y = fmaxf(acc[i][1] + bv.y, 0.0f);
            o.z = fmaxf(acc[i][2] + bv.z, 0.0f);
            o.w = fmaxf(acc[i][3] + bv.w, 0.0f);
            *(float4*)(g_T + gn * D + f0) = o;
        }
    }
}

// ---------------- BN statistics over g_T ----------------
__global__ __launch_bounds__(240) void k_bnstats(int NN) {
    __shared__ double shs[240];
    __shared__ double shq[240];
    int t = threadIdx.x;
    int f = t % D;
    int s = t / D;  // 0..4
    double ds = 0.0, dq = 0.0;
    for (int n = blockIdx.x * 5 + s; n < NN; n += gridDim.x * 5) {
        float v = g_T[n * D + f];
        ds += (double)v;
        dq += (double)v * (double)v;
    }
    shs[t] = ds;
    shq[t] = dq;
    __syncthreads();
    if (s == 0) {
#pragma unroll
        for (int j = 1; j < 5; j++) {
            ds += shs[j * D + f];
            dq += shq[j * D + f];
        }
        atomicAdd(&g_bnsum[f], ds);
        atomicAdd(&g_bnsq[f], dq);
    }
}

__global__ void k_bnfin(const float* __restrict__ gamma,
                        const float* __restrict__ beta, int NN) {
    int f = threadIdx.x;
    if (f < D) {
        double mean = g_bnsum[f] / (double)NN;
        double var = g_bnsq[f] / (double)NN - mean * mean;
        float a = gamma[f] * rsqrtf((float)var + BN_EPS);
        g_a[f] = a;
        g_c[f] = beta[f] - (float)mean * a;
        g_bnsum[f] = 0.0;  // reset for next iteration / next replay
        g_bnsq[f] = 0.0;
    }
}

// ---------------- graph boundaries (batch is sorted) ----------------
__global__ void k_gstart(const void* __restrict__ batch, int NN) {
    int is64 = g_is64;
    int i = blockIdx.x * blockDim.x + threadIdx.x;
    if (i > NN) return;
    int bi = (i < NN) ? idx_get(batch, i, is64) : NGRAPH;
    int bp = (i > 0) ? idx_get(batch, i - 1, is64) : -1;
    if (bi < 0) bi = 0;
    if (bi > NGRAPH) bi = NGRAPH;
    if (bp < -1) bp = -1;
    if (bp > NGRAPH) bp = NGRAPH;
    for (int g = bp + 1; g <= bi; g++) g_gstart[g] = i;
}

// ---------------- global add pool: one block per graph ----------------
__global__ __launch_bounds__(240) void k_gsum() {
    __shared__ float sh[5 * D];
    int g = blockIdx.x;
    int t = threadIdx.x;
    int f = t % D;
    int s = t / D;  // 0..4
    int st = g_gstart[g], en = g_gstart[g + 1];
    float acc = 0.0f;
    for (int n = st + s; n < en; n += 5) acc += g_X[n * D + f];
    sh[s * D + f] = acc;
    __syncthreads();
    if (t < D) {
        float v = sh[t] + sh[D + t] + sh[2 * D + t] + sh[3 * D + t] + sh[4 * D + t];
        g_g[g * D + t] = v;
    }
}

// ---------------- final MLP: one block per graph ----------------
__global__ __launch_bounds__(128) void k_mlp(const float* __restrict__ W1,
                                             const float* __restrict__ b1,
                                             const float* __restrict__ W2,
                                             const float* __restrict__ b2,
                                             float* __restrict__ out) {
    __shared__ float gr[D];
    __shared__ float hs[128];
    int g = blockIdx.x;
    int t = threadIdx.x;
    if (t < D) gr[t] = g_g[g * D + t];
    __syncthreads();
    float a = b1[t];
#pragma unroll
    for (int k = 0; k < D; k++) a = fmaf(gr[k], W1[k * 128 + t], a);
    hs[t] = fmaxf(a, 0.0f);
    __syncthreads();
    if (t < 12) {
        float o = b2[t];
#pragma unroll
        for (int j = 0; j < 128; j++) o = fmaf(hs[j], W2[j * 12 + t], o);
        out[g * 12 + t] = o;
    }
}

// ---------------- host orchestration ----------------
extern "C" void kernel_launch(void* const* d_in, const int* in_sizes, int n_in,
                              void* d_out, int out_size) {
    const float* x    = (const float*)d_in[0];
    const void* ei    = d_in[1];
    const void* batch = d_in[2];
    // num_graphs may appear as a tiny scalar buffer between batch and W.
    // W has K*D*D = 6912 elements; detect by size.
    int base = 3;
    if (n_in >= 12 && in_sizes[3] < 100) base = 4;
    const float* W     = (const float*)d_in[base + 0];
    const float* b     = (const float*)d_in[base + 1];
    const float* gamma = (const float*)d_in[base + 2];
    const float* beta  = (const float*)d_in[base + 3];
    const float* W1    = (const float*)d_in[base + 4];
    const float* b1    = (const float*)d_in[base + 5];
    const float* W2    = (const float*)d_in[base + 6];
    const float* b2    = (const float*)d_in[base + 7];

    int NN = in_sizes[0] / D;
    int EE = in_sizes[1] / 2;
    if (NN > NMAX) NN = NMAX;
    if (EE > EMAX) EE = EMAX;

    // Preprocessing: dtype detect, degrees, dinv, CSR bucketing, boundaries.
    k_detect<<<1, 256>>>(ei, EE, NN);
    k_init<<<2048, 256>>>(x, NN);
    k_count<<<2048, 256>>>(ei, EE, NN);
    k_dinv<<<(NN + 255) / 256, 256>>>(NN);
    int NB = (NN + 1023) / 1024;
    k_scan1<<<NB, 1024>>>(NN);
    k_scan2<<<1, 128>>>(NB);
    k_scan3<<<NB, 1024>>>(NN, EE);
    k_bucket<<<2048, 256>>>(ei, EE, NN);
    k_gstart<<<(NN + 256) / 256, 256>>>(batch, NN);

    dim3 gb(48, 8);
    int ggrid = (NN + 7) / 8;
    int gemm_grid = (NN + TILE_N - 1) / TILE_N;
    int ps_grid = 1184;

    for (int it = 0; it < NSTEPS; it++) {
        k_prescale<0><<<ps_grid, 256>>>(NN);            // Y = dinv*X
        k_gather<0><<<ggrid, gb>>>(NN);                 // Tx1 = lhat(X)
        k_prescale<1><<<ps_grid, 256>>>(NN);            // Y = dinv*T1
        k_gather<1><<<ggrid, gb>>>(NN);                 // Tx2 = 2*lhat(Tx1) - X
        k_gemm<<<gemm_grid, 192>>>(W, b, NN);           // T = relu(cheb)
        k_bnstats<<<296, 240>>>(NN);                    // sums for BN
        k_bnfin<<<1, 64>>>(gamma, beta, NN);            // a, c; reset sums
        k_gather<2><<<ggrid, gb>>>(NN);                 // X = pool(BN(T))
    }

    k_gsum<<<NGRAPH, 240>>>();
    k_mlp<<<NGRAPH, 128>>>(W1, b1, W2, b2, (float*)d_out);
}

// round 5
// speedup vs baseline: 2.0286x; 2.0286x over previous
#include <cuda_runtime.h>
#include <cuda_bf16.h>
#include <stdint.h>

#define NMAX 100000
#define EMAX 1600000
#define D 48
#define D4 12
#define NSTEPS 5
#define NGRAPH 64
#define BN_EPS 1e-5f

// ---------------- device scratch (static: allocation-free rule) ----------------
__device__ int   g_is64;
__device__ int   g_deg[NMAX];
__device__ float g_dinv[NMAX];
__device__ int   g_rowstart[NMAX + 1];
__device__ int   g_wp[NMAX];
__device__ int   g_ecol[EMAX];
__device__ int   g_scanblk[256];
__device__ int   g_scanoff[256];
__device__ __align__(16) float g_X [NMAX * D];   // current node features
__device__ __align__(16) float g_Y [NMAX * D];   // dinv*X   (gather0 source)
__device__ __align__(16) float g_Y2[NMAX * D];   // dinv*T1  (gather1 source)
__device__ __align__(16) float g_T1[NMAX * D];   // Tx1
__device__ __align__(16) float g_T2[NMAX * D];   // Tx2
__device__ __align__(16) float g_T [NMAX * D];   // relu(cheb) output
__device__ double g_bnsum[D];
__device__ double g_bnsq[D];
__device__ __align__(16) float g_a[D];
__device__ __align__(16) float g_c[D];
__device__ float g_g[NGRAPH * D];
__device__ int   g_gstart[NGRAPH + 1];

// ---------------- small float4 helpers ----------------
__device__ __forceinline__ float4 f4add(float4 a, float4 b) {
    return make_float4(a.x + b.x, a.y + b.y, a.z + b.z, a.w + b.w);
}
__device__ __forceinline__ float4 f4max(float4 a, float4 b) {
    return make_float4(fmaxf(a.x, b.x), fmaxf(a.y, b.y), fmaxf(a.z, b.z),
                       fmaxf(a.w, b.w));
}
__device__ __forceinline__ float4 f4fma(float4 a, float4 v, float4 c) {
    return make_float4(fmaf(a.x, v.x, c.x), fmaf(a.y, v.y, c.y),
                       fmaf(a.z, v.z, c.z), fmaf(a.w, v.w, c.w));
}
__device__ __forceinline__ float4 f4scale(float s, float4 v) {
    return make_float4(s * v.x, s * v.y, s * v.z, s * v.w);
}

__device__ __forceinline__ int idx_get(const void* p, int i, int is64) {
    return is64 ? (int)((const long long*)p)[i] : ((const int*)p)[i];
}

// ---------------- init: copy x, zero deg, detect edge dtype (block 0) -------
__global__ void k_init(const float* __restrict__ x, const void* ei, int NN,
                       int EE) {
    if (blockIdx.x == 0) {
        // dtype probe: EE int64 reads span exactly the int32 buffer (2*EE elts)
        const long long* p = (const long long*)ei;
        int stride = EE / 256;
        if (stride < 1) stride = 1;
        int e = threadIdx.x * stride;
        int ok = 1;
        if (e < EE) {
            long long v = p[e];
            if (v < 0 || v >= (long long)NN) ok = 0;
        }
        int all = __syncthreads_and(ok);
        if (threadIdx.x == 0) g_is64 = all;
    }
    int total = NN * D4;
    for (int i = blockIdx.x * blockDim.x + threadIdx.x; i < total;
         i += gridDim.x * blockDim.x) {
        ((float4*)g_X)[i] = ((const float4*)x)[i];
        if (i < NN) g_deg[i] = 0;
    }
}

__global__ void k_count(const void* __restrict__ ei, int EE, int NN) {
    int is64 = g_is64;
    for (int e = blockIdx.x * blockDim.x + threadIdx.x; e < EE;
         e += gridDim.x * blockDim.x) {
        int r = idx_get(ei, e, is64);
        if ((unsigned)r < (unsigned)NN) atomicAdd(&g_deg[r], 1);
    }
}

// ---------------- 3-kernel exclusive prefix scan over deg (+dinv) -----------
__global__ void k_scan1(int NN) {
    __shared__ int sh[1024];
    int t = threadIdx.x;
    int i = blockIdx.x * 1024 + t;
    int v = (i < NN) ? g_deg[i] : 0;
    sh[t] = v;
    __syncthreads();
    for (int off = 1; off < 1024; off <<= 1) {
        int tv = (t >= off) ? sh[t - off] : 0;
        __syncthreads();
        sh[t] += tv;
        __syncthreads();
    }
    if (i < NN) {
        g_rowstart[i] = sh[t] - v;  // exclusive, pre-offset
        g_dinv[i] = (v > 0) ? rsqrtf((float)v) : 0.0f;
    }
    if (t == 1023) g_scanblk[blockIdx.x] = sh[1023];
}

__global__ void k_scan2(int NB) {
    __shared__ int sh[128];
    int t = threadIdx.x;
    int v = (t < NB) ? g_scanblk[t] : 0;
    sh[t] = v;
    __syncthreads();
    for (int off = 1; off < 128; off <<= 1) {
        int tv = (t >= off) ? sh[t - off] : 0;
        __syncthreads();
        sh[t] += tv;
        __syncthreads();
    }
    g_scanoff[t] = sh[t] - v;
}

__global__ void k_scan3(int NN, int EE) {
    int i = blockIdx.x * 1024 + threadIdx.x;
    if (i < NN) {
        int rs = g_rowstart[i] + g_scanoff[blockIdx.x];
        g_rowstart[i] = rs;
        g_wp[i] = rs;
    }
    if (i == 0) g_rowstart[NN] = EE;
}

__global__ void k_bucket(const void* __restrict__ ei, int EE, int NN) {
    int is64 = g_is64;
    for (int e = blockIdx.x * blockDim.x + threadIdx.x; e < EE;
         e += gridDim.x * blockDim.x) {
        int r = idx_get(ei, e, is64);
        int c = idx_get(ei, EE + e, is64);
        if ((unsigned)r < (unsigned)NN && (unsigned)c < (unsigned)NN) {
            int p = atomicAdd(&g_wp[r], 1);
            if ((unsigned)p < (unsigned)EMAX) g_ecol[p] = c;
        }
    }
}

// ---------------- one-time prescale: Y = dinv * X ----------------
__global__ __launch_bounds__(256) void k_prescale(int NN) {
    int total = NN * D4;
    for (int i = blockIdx.x * blockDim.x + threadIdx.x; i < total;
         i += gridDim.x * blockDim.x) {
        ((float4*)g_Y)[i] = f4scale(g_dinv[i / D4], ((const float4*)g_X)[i]);
    }
}

// ---------------- CSR gather kernels (float4 lanes, 4-way unroll) ----------
// MODE 0: T1 = -dinv*sum(Y[c]);  Y2 = dinv*T1
// MODE 1: T2 = -2*dinv*sum(Y2[c]) - X
// MODE 2: X = deg>0 ? max_c(a*T[c]+c) : 0;  Y = dinv*X
template <int MODE>
__global__ __launch_bounds__(384) void k_gather(int NN) {
    int row = blockIdx.x * 32 + threadIdx.y;
    if (row >= NN) return;
    int f = threadIdx.x;  // 0..11
    int s = g_rowstart[row];
    int e = g_rowstart[row + 1];
    const float4* __restrict__ src =
        (MODE == 0) ? (const float4*)g_Y
                    : (MODE == 1) ? (const float4*)g_Y2 : (const float4*)g_T;
    const int* __restrict__ ec = g_ecol;

    if (MODE == 2) {
        float4 av = ((const float4*)g_a)[f];
        float4 cv = ((const float4*)g_c)[f];
        float NI = __int_as_float(0xff800000);
        float4 m0 = make_float4(NI, NI, NI, NI), m1 = m0, m2 = m0, m3 = m0;
        int i = s;
        for (; i + 4 <= e; i += 4) {
            int c0 = __ldg(ec + i), c1 = __ldg(ec + i + 1);
            int c2 = __ldg(ec + i + 2), c3 = __ldg(ec + i + 3);
            float4 v0 = __ldg(src + c0 * D4 + f);
            float4 v1 = __ldg(src + c1 * D4 + f);
            float4 v2 = __ldg(src + c2 * D4 + f);
            float4 v3 = __ldg(src + c3 * D4 + f);
            m0 = f4max(m0, f4fma(av, v0, cv));
            m1 = f4max(m1, f4fma(av, v1, cv));
            m2 = f4max(m2, f4fma(av, v2, cv));
            m3 = f4max(m3, f4fma(av, v3, cv));
        }
        for (; i < e; i++) {
            int c = __ldg(ec + i);
            m0 = f4max(m0, f4fma(av, __ldg(src + c * D4 + f), cv));
        }
        float4 m = f4max(f4max(m0, m1), f4max(m2, m3));
        float4 xv = (e > s) ? m : make_float4(0.f, 0.f, 0.f, 0.f);
        ((float4*)g_X)[row * D4 + f] = xv;
        ((float4*)g_Y)[row * D4 + f] = f4scale(g_dinv[row], xv);
    } else {
        float4 a0 = make_float4(0.f, 0.f, 0.f, 0.f), a1 = a0, a2 = a0, a3 = a0;
        int i = s;
        for (; i + 4 <= e; i += 4) {
            int c0 = __ldg(ec + i), c1 = __ldg(ec + i + 1);
            int c2 = __ldg(ec + i + 2), c3 = __ldg(ec + i + 3);
            a0 = f4add(a0, __ldg(src + c0 * D4 + f));
            a1 = f4add(a1, __ldg(src + c1 * D4 + f));
            a2 = f4add(a2, __ldg(src + c2 * D4 + f));
            a3 = f4add(a3, __ldg(src + c3 * D4 + f));
        }
        for (; i < e; i++) {
            int c = __ldg(ec + i);
            a0 = f4add(a0, __ldg(src + c * D4 + f));
        }
        float4 sum = f4add(f4add(a0, a1), f4add(a2, a3));
        float dr = g_dinv[row];
        if (MODE == 0) {
            float4 t1 = f4scale(-dr, sum);
            ((float4*)g_T1)[row * D4 + f] = t1;
            ((float4*)g_Y2)[row * D4 + f] = f4scale(dr, t1);
        } else {
            float4 xr = __ldg((const float4*)g_X + row * D4 + f);
            float4 t2;
            float nd = -2.0f * dr;
            t2.x = fmaf(nd, sum.x, -xr.x);
            t2.y = fmaf(nd, sum.y, -xr.y);
            t2.z = fmaf(nd, sum.z, -xr.z);
            t2.w = fmaf(nd, sum.w, -xr.w);
            ((float4*)g_T2)[row * D4 + f] = t2;
        }
    }
}

// ------- fused cheb GEMM + BN stats: T = relu(X@W0+T1@W1+T2@W2+b) -----------
#define TILE_N 64
#define XS_STRIDE 68

__global__ __launch_bounds__(192) void k_gemm(const float* __restrict__ W,
                                              const float* __restrict__ b,
                                              int NN) {
    __shared__ float xs[144 * XS_STRIDE];
    __shared__ float bsum[48], bsq[48];
    int tid = threadIdx.x;
    int f_id = tid % 12;
    int n_id = tid / 12;
    int f0 = f_id * 4;
    int n0 = n_id * 4;

    if (tid < 48) { bsum[tid] = 0.f; bsq[tid] = 0.f; }

    int nodebase = blockIdx.x * TILE_N;

    for (int v = tid; v < 3 * TILE_N * 12; v += 192) {
        int buf = v / (TILE_N * 12);
        int rem = v % (TILE_N * 12);
        int node = rem / 12;
        int c4 = rem % 12;
        const float* sp = (buf == 0) ? g_X : (buf == 1) ? g_T1 : g_T2;
        float4 val = make_float4(0.f, 0.f, 0.f, 0.f);
        int gn = nodebase + node;
        if (gn < NN) val = *(const float4*)(sp + gn * D + c4 * 4);
        int kb = buf * 48 + c4 * 4;
        xs[(kb + 0) * XS_STRIDE + node] = val.x;
        xs[(kb + 1) * XS_STRIDE + node] = val.y;
        xs[(kb + 2) * XS_STRIDE + node] = val.z;
        xs[(kb + 3) * XS_STRIDE + node] = val.w;
    }
    __syncthreads();

    float acc[4][4];
#pragma unroll
    for (int i = 0; i < 4; i++)
#pragma unroll
        for (int j = 0; j < 4; j++) acc[i][j] = 0.0f;

#pragma unroll 4
    for (int k = 0; k < 144; k++) {
        float4 wv = __ldg((const float4*)(W + k * 48 + f0));
        float4 xv = *(const float4*)&xs[k * XS_STRIDE + n0];
        acc[0][0] = fmaf(xv.x, wv.x, acc[0][0]);
        acc[0][1] = fmaf(xv.x, wv.y, acc[0][1]);
        acc[0][2] = fmaf(xv.x, wv.z, acc[0][2]);
        acc[0][3] = fmaf(xv.x, wv.w, acc[0][3]);
        acc[1][0] = fmaf(xv.y, wv.x, acc[1][0]);
        acc[1][1] = fmaf(xv.y, wv.y, acc[1][1]);
        acc[1][2] = fmaf(xv.y, wv.z, acc[1][2]);
        acc[1][3] = fmaf(xv.y, wv.w, acc[1][3]);
        acc[2][0] = fmaf(xv.z, wv.x, acc[2][0]);
        acc[2][1] = fmaf(xv.z, wv.y, acc[2][1]);
        acc[2][2] = fmaf(xv.z, wv.z, acc[2][2]);
        acc[2][3] = fmaf(xv.z, wv.w, acc[2][3]);
        acc[3][0] = fmaf(xv.w, wv.x, acc[3][0]);
        acc[3][1] = fmaf(xv.w, wv.y, acc[3][1]);
        acc[3][2] = fmaf(xv.w, wv.z, acc[3][2]);
        acc[3][3] = fmaf(xv.w, wv.w, acc[3][3]);
    }

    float4 bv = __ldg((const float4*)(b + f0));
    float4 ps = make_float4(0.f, 0.f, 0.f, 0.f);
    float4 pq = ps;
#pragma unroll
    for (int i = 0; i < 4; i++) {
        int gn = nodebase + n0 + i;
        if (gn < NN) {
            float4 o;
            o.x = fmaxf(acc[i][0] + bv.x, 0.0f);
            o.y = fmaxf(acc[i][1] + bv.y, 0.0f);
            o.z = fmaxf(acc[i][2] + bv.z, 0.0f);
            o.w = fmaxf(acc[i][3] + bv.w, 0.0f);
            *(float4*)(g_T + gn * D + f0) = o;
            ps = f4add(ps, o);
            pq.x = fmaf(o.x, o.x, pq.x);
            pq.y = fmaf(o.y, o.y, pq.y);
            pq.z = fmaf(o.z, o.z, pq.z);
            pq.w = fmaf(o.w, o.w, pq.w);
        }
    }
    atomicAdd(&bsum[f0 + 0], ps.x);
    atomicAdd(&bsum[f0 + 1], ps.y);
    atomicAdd(&bsum[f0 + 2], ps.z);
    atomicAdd(&bsum[f0 + 3], ps.w);
    atomicAdd(&bsq[f0 + 0], pq.x);
    atomicAdd(&bsq[f0 + 1], pq.y);
    atomicAdd(&bsq[f0 + 2], pq.z);
    atomicAdd(&bsq[f0 + 3], pq.w);
    __syncthreads();
    if (tid < 48) {
        atomicAdd(&g_bnsum[tid], (double)bsum[tid]);
        atomicAdd(&g_bnsq[tid], (double)bsq[tid]);
    }
}

__global__ void k_bnfin(const float* __restrict__ gamma,
                        const float* __restrict__ beta, int NN) {
    int f = threadIdx.x;
    if (f < D) {
        double mean = g_bnsum[f] / (double)NN;
        double var = g_bnsq[f] / (double)NN - mean * mean;
        float a = gamma[f] * rsqrtf((float)var + BN_EPS);
        g_a[f] = a;
        g_c[f] = beta[f] - (float)mean * a;
        g_bnsum[f] = 0.0;  // reset for next iteration / next replay
        g_bnsq[f] = 0.0;
    }
}

// ---------------- graph boundaries (batch is sorted) ----------------
__global__ void k_gstart(const void* __restrict__ batch, int NN) {
    int is64 = g_is64;
    int i = blockIdx.x * blockDim.x + threadIdx.x;
    if (i > NN) return;
    int bi = (i < NN) ? idx_get(batch, i, is64) : NGRAPH;
    int bp = (i > 0) ? idx_get(batch, i - 1, is64) : -1;
    if (bi < 0) bi = 0;
    if (bi > NGRAPH) bi = NGRAPH;
    if (bp < -1) bp = -1;
    if (bp > NGRAPH) bp = NGRAPH;
    for (int g = bp + 1; g <= bi; g++) g_gstart[g] = i;
}

// ---------------- global add pool: one block per graph ----------------
__global__ __launch_bounds__(240) void k_gsum() {
    __shared__ float sh[5 * D];
    int g = blockIdx.x;
    int t = threadIdx.x;
    int f = t % D;
    int s = t / D;  // 0..4
    int st = g_gstart[g], en = g_gstart[g + 1];
    float acc = 0.0f;
    for (int n = st + s; n < en; n += 5) acc += g_X[n * D + f];
    sh[s * D + f] = acc;
    __syncthreads();
    if (t < D) {
        float v = sh[t] + sh[D + t] + sh[2 * D + t] + sh[3 * D + t] + sh[4 * D + t];
        g_g[g * D + t] = v;
    }
}

// ---------------- final MLP: one block per graph ----------------
__global__ __launch_bounds__(128) void k_mlp(const float* __restrict__ W1,
                                             const float* __restrict__ b1,
                                             const float* __restrict__ W2,
                                             const float* __restrict__ b2,
                                             float* __restrict__ out) {
    __shared__ float gr[D];
    __shared__ float hs[128];
    int g = blockIdx.x;
    int t = threadIdx.x;
    if (t < D) gr[t] = g_g[g * D + t];
    __syncthreads();
    float a = b1[t];
#pragma unroll
    for (int k = 0; k < D; k++) a = fmaf(gr[k], W1[k * 128 + t], a);
    hs[t] = fmaxf(a, 0.0f);
    __syncthreads();
    if (t < 12) {
        float o = b2[t];
#pragma unroll
        for (int j = 0; j < 128; j++) o = fmaf(hs[j], W2[j * 12 + t], o);
        out[g * 12 + t] = o;
    }
}

// ---------------- host orchestration ----------------
extern "C" void kernel_launch(void* const* d_in, const int* in_sizes, int n_in,
                              void* d_out, int out_size) {
    const float* x    = (const float*)d_in[0];
    const void* ei    = d_in[1];
    const void* batch = d_in[2];
    int base = 3;
    if (n_in >= 12 && in_sizes[3] < 100) base = 4;
    const float* W     = (const float*)d_in[base + 0];
    const float* b     = (const float*)d_in[base + 1];
    const float* gamma = (const float*)d_in[base + 2];
    const float* beta  = (const float*)d_in[base + 3];
    const float* W1    = (const float*)d_in[base + 4];
    const float* b1    = (const float*)d_in[base + 5];
    const float* W2    = (const float*)d_in[base + 6];
    const float* b2    = (const float*)d_in[base + 7];

    int NN = in_sizes[0] / D;
    int EE = in_sizes[1] / 2;
    if (NN > NMAX) NN = NMAX;
    if (EE > EMAX) EE = EMAX;

    k_init<<<2048, 256>>>(x, ei, NN, EE);     // copy + zero deg + dtype detect
    k_count<<<2048, 256>>>(ei, EE, NN);
    int NB = (NN + 1023) / 1024;
    k_scan1<<<NB, 1024>>>(NN);                // scan + dinv
    k_scan2<<<1, 128>>>(NB);
    k_scan3<<<NB, 1024>>>(NN, EE);
    k_bucket<<<2048, 256>>>(ei, EE, NN);
    k_gstart<<<(NN + 256) / 256, 256>>>(batch, NN);
    k_prescale<<<1184, 256>>>(NN);            // Y = dinv*X (once)

    dim3 gb(12, 32);
    int ggrid = (NN + 31) / 32;
    int gemm_grid = (NN + TILE_N - 1) / TILE_N;

    for (int it = 0; it < NSTEPS; it++) {
        k_gather<0><<<ggrid, gb>>>(NN);       // T1, Y2=dinv*T1
        k_gather<1><<<ggrid, gb>>>(NN);       // T2
        k_gemm<<<gemm_grid, 192>>>(W, b, NN); // T = relu(cheb), BN stats fused
        k_bnfin<<<1, 64>>>(gamma, beta, NN);  // a, c; reset sums
        k_gather<2><<<ggrid, gb>>>(NN);       // X = pool(BN(T)), Y=dinv*X
    }

    k_gsum<<<NGRAPH, 240>>>();
    k_mlp<<<NGRAPH, 128>>>(W1, b1, W2, b2, (float*)d_out);
}

// round 6
// speedup vs baseline: 2.1227x; 1.0464x over previous
#include <cuda_runtime.h>
#include <cuda_bf16.h>
#include <cuda_fp16.h>
#include <stdint.h>

#define NMAX 100000
#define EMAX 1600000
#define D 48
#define D4 12
#define HSTRIDE 64   // halfs per row (48 used, padded to 128 B)
#define HS2 16       // uint2 per row
#define NSTEPS 5
#define NGRAPH 64
#define DEGB 512
#define BN_EPS 1e-5f

// ---------------- device scratch (static: allocation-free rule) ----------------
__device__ int   g_is64;
__device__ int   g_deg[NMAX];
__device__ float g_dinv[NMAX];
__device__ int   g_rowstart[NMAX + 1];
__device__ int   g_wp[NMAX];
__device__ int   g_ecol[EMAX];
__device__ int   g_scanblk[256];
__device__ int   g_scanoff[256];
__device__ int   g_dhist[DEGB];
__device__ int   g_doff[DEGB];
__device__ int   g_perm[NMAX];
__device__ __align__(16) float  g_X [NMAX * D];       // pool output (fp32)
__device__ __align__(16) float  g_T1[NMAX * D];       // Tx1 (fp32)
__device__ __align__(16) float  g_T2[NMAX * D];       // Tx2 (fp32)
__device__ __align__(16) __half g_Yh [NMAX * HSTRIDE]; // dinv*X  (gather0 src)
__device__ __align__(16) __half g_Y2h[NMAX * HSTRIDE]; // dinv*T1 (gather1 src)
__device__ __align__(16) __half g_Th [NMAX * HSTRIDE]; // relu(cheb) (pool src)
__device__ double g_bnsum[D];
__device__ double g_bnsq[D];
__device__ __align__(16) float g_a[D];
__device__ __align__(16) float g_c[D];
__device__ float g_g[NGRAPH * D];
__device__ int   g_gstart[NGRAPH + 1];

// ---------------- helpers ----------------
__device__ __forceinline__ float4 f4add(float4 a, float4 b) {
    return make_float4(a.x + b.x, a.y + b.y, a.z + b.z, a.w + b.w);
}
__device__ __forceinline__ float4 f4max(float4 a, float4 b) {
    return make_float4(fmaxf(a.x, b.x), fmaxf(a.y, b.y), fmaxf(a.z, b.z),
                       fmaxf(a.w, b.w));
}
__device__ __forceinline__ float4 f4fma(float4 a, float4 v, float4 c) {
    return make_float4(fmaf(a.x, v.x, c.x), fmaf(a.y, v.y, c.y),
                       fmaf(a.z, v.z, c.z), fmaf(a.w, v.w, c.w));
}
__device__ __forceinline__ float4 f4scale(float s, float4 v) {
    return make_float4(s * v.x, s * v.y, s * v.z, s * v.w);
}
__device__ __forceinline__ float4 h4_to_f4(uint2 v) {
    __half2 h0 = *(__half2*)&v.x;
    __half2 h1 = *(__half2*)&v.y;
    float2 f0 = __half22float2(h0);
    float2 f1 = __half22float2(h1);
    return make_float4(f0.x, f0.y, f1.x, f1.y);
}
__device__ __forceinline__ uint2 f4_to_h4(float4 f) {
    __half2 h0 = __floats2half2_rn(f.x, f.y);
    __half2 h1 = __floats2half2_rn(f.z, f.w);
    uint2 r;
    r.x = *(unsigned*)&h0;
    r.y = *(unsigned*)&h1;
    return r;
}
__device__ __forceinline__ int idx_get(const void* p, int i, int is64) {
    return is64 ? (int)((const long long*)p)[i] : ((const int*)p)[i];
}

// ---------------- init: copy x, zero deg/hist, detect edge dtype ----------
__global__ void k_init(const float* __restrict__ x, const void* ei, int NN,
                       int EE) {
    if (blockIdx.x == 0) {
        const long long* p = (const long long*)ei;
        int stride = EE / 256;
        if (stride < 1) stride = 1;
        int e = threadIdx.x * stride;
        int ok = 1;
        if (e < EE) {
            long long v = p[e];
            if (v < 0 || v >= (long long)NN) ok = 0;
        }
        int all = __syncthreads_and(ok);
        if (threadIdx.x == 0) g_is64 = all;
    }
    int gt = blockIdx.x * blockDim.x + threadIdx.x;
    if (gt < DEGB) g_dhist[gt] = 0;
    int total = NN * D4;
    for (int i = gt; i < total; i += gridDim.x * blockDim.x) {
        ((float4*)g_X)[i] = ((const float4*)x)[i];
        if (i < NN) g_deg[i] = 0;
    }
}

__global__ void k_count(const void* __restrict__ ei, int EE, int NN) {
    int is64 = g_is64;
    for (int e = blockIdx.x * blockDim.x + threadIdx.x; e < EE;
         e += gridDim.x * blockDim.x) {
        int r = idx_get(ei, e, is64);
        if ((unsigned)r < (unsigned)NN) atomicAdd(&g_deg[r], 1);
    }
}

// ---------------- prefix scan over deg (+dinv +degree histogram) -----------
__global__ void k_scan1(int NN) {
    __shared__ int sh[1024];
    __shared__ int hist[DEGB];
    int t = threadIdx.x;
    if (t < DEGB) hist[t] = 0;
    int i = blockIdx.x * 1024 + t;
    int v = (i < NN) ? g_deg[i] : 0;
    sh[t] = v;
    __syncthreads();
    for (int off = 1; off < 1024; off <<= 1) {
        int tv = (t >= off) ? sh[t - off] : 0;
        __syncthreads();
        sh[t] += tv;
        __syncthreads();
    }
    if (i < NN) {
        g_rowstart[i] = sh[t] - v;  // exclusive, pre-offset
        g_dinv[i] = (v > 0) ? rsqrtf((float)v) : 0.0f;
        atomicAdd(&hist[v < DEGB ? v : DEGB - 1], 1);
    }
    if (t == 1023) g_scanblk[blockIdx.x] = sh[1023];
    __syncthreads();
    if (t < DEGB && hist[t] > 0) atomicAdd(&g_dhist[t], hist[t]);
}

__global__ void k_scan2(int NB) {
    __shared__ int sh[128];
    int t = threadIdx.x;
    int v = (t < NB) ? g_scanblk[t] : 0;
    sh[t] = v;
    __syncthreads();
    for (int off = 1; off < 128; off <<= 1) {
        int tv = (t >= off) ? sh[t - off] : 0;
        __syncthreads();
        sh[t] += tv;
        __syncthreads();
    }
    g_scanoff[t] = sh[t] - v;
}

__global__ void k_scan3(int NN, int EE) {
    int i = blockIdx.x * 1024 + threadIdx.x;
    if (i < NN) {
        int rs = g_rowstart[i] + g_scanoff[blockIdx.x];
        g_rowstart[i] = rs;
        g_wp[i] = rs;
    }
    if (i == 0) g_rowstart[NN] = EE;
}

// ---------------- degree counting sort: perm ----------------
__global__ void k_dscan() {  // exclusive scan of g_dhist -> g_doff (1 block)
    __shared__ int sh[DEGB];
    int t = threadIdx.x;
    int v = g_dhist[t];
    sh[t] = v;
    __syncthreads();
    for (int off = 1; off < DEGB; off <<= 1) {
        int tv = (t >= off) ? sh[t - off] : 0;
        __syncthreads();
        sh[t] += tv;
        __syncthreads();
    }
    g_doff[t] = sh[t] - v;
}

__global__ void k_dscatter(int NN) {
    __shared__ int lh[DEGB];
    __shared__ int lbase[DEGB];
    int t = threadIdx.x;  // 512
    lh[t] = 0;
    __syncthreads();
    int i = blockIdx.x * 512 + t;
    int d = 0, lr = 0;
    if (i < NN) {
        d = g_deg[i];
        if (d >= DEGB) d = DEGB - 1;
        lr = atomicAdd(&lh[d], 1);
    }
    __syncthreads();
    if (lh[t] > 0) lbase[t] = atomicAdd(&g_doff[t], lh[t]);
    __syncthreads();
    if (i < NN) g_perm[lbase[d] + lr] = i;
}

__global__ void k_bucket(const void* __restrict__ ei, int EE, int NN) {
    int is64 = g_is64;
    for (int e = blockIdx.x * blockDim.x + threadIdx.x; e < EE;
         e += gridDim.x * blockDim.x) {
        int r = idx_get(ei, e, is64);
        int c = idx_get(ei, EE + e, is64);
        if ((unsigned)r < (unsigned)NN && (unsigned)c < (unsigned)NN) {
            int p = atomicAdd(&g_wp[r], 1);
            if ((unsigned)p < (unsigned)EMAX) g_ecol[p] = c;
        }
    }
}

// ---------------- one-time prescale: Yh = half(dinv * X) ----------------
__global__ __launch_bounds__(256) void k_prescale(int NN) {
    int total = NN * D4;
    for (int i = blockIdx.x * blockDim.x + threadIdx.x; i < total;
         i += gridDim.x * blockDim.x) {
        int row = i / D4, f = i % D4;
        float4 v = f4scale(g_dinv[row], ((const float4*)g_X)[i]);
        ((uint2*)g_Yh)[row * HS2 + f] = f4_to_h4(v);
    }
}

// ---------------- CSR gather kernels (fp16 src, degree-sorted rows) --------
// MODE 0: T1 = -dinv*sum(Yh[c]);  Y2h = dinv*T1
// MODE 1: T2 = -2*dinv*sum(Y2h[c]) - X
// MODE 2: X = deg>0 ? max_c(a*Th[c]+c) : 0;  Yh = dinv*X
template <int MODE>
__global__ __launch_bounds__(384) void k_gather(int NN) {
    int vrow = blockIdx.x * 32 + threadIdx.y;
    if (vrow >= NN) return;
    int row = g_perm[vrow];
    int f = threadIdx.x;  // 0..11
    int s = g_rowstart[row];
    int e = g_rowstart[row + 1];
    const uint2* __restrict__ src =
        (MODE == 0) ? (const uint2*)g_Yh
                    : (MODE == 1) ? (const uint2*)g_Y2h : (const uint2*)g_Th;
    const int* __restrict__ ec = g_ecol;

    if (MODE == 2) {
        float4 av = ((const float4*)g_a)[f];
        float4 cv = ((const float4*)g_c)[f];
        float NI = __int_as_float(0xff800000);
        float4 m0 = make_float4(NI, NI, NI, NI), m1 = m0, m2 = m0, m3 = m0;
        int i = s;
        for (; i + 4 <= e; i += 4) {
            int c0 = __ldg(ec + i), c1 = __ldg(ec + i + 1);
            int c2 = __ldg(ec + i + 2), c3 = __ldg(ec + i + 3);
            float4 v0 = h4_to_f4(__ldg(src + c0 * HS2 + f));
            float4 v1 = h4_to_f4(__ldg(src + c1 * HS2 + f));
            float4 v2 = h4_to_f4(__ldg(src + c2 * HS2 + f));
            float4 v3 = h4_to_f4(__ldg(src + c3 * HS2 + f));
            m0 = f4max(m0, f4fma(av, v0, cv));
            m1 = f4max(m1, f4fma(av, v1, cv));
            m2 = f4max(m2, f4fma(av, v2, cv));
            m3 = f4max(m3, f4fma(av, v3, cv));
        }
        for (; i < e; i++) {
            int c = __ldg(ec + i);
            m0 = f4max(m0, f4fma(av, h4_to_f4(__ldg(src + c * HS2 + f)), cv));
        }
        float4 m = f4max(f4max(m0, m1), f4max(m2, m3));
        float4 xv = (e > s) ? m : make_float4(0.f, 0.f, 0.f, 0.f);
        ((float4*)g_X)[row * D4 + f] = xv;
        ((uint2*)g_Yh)[row * HS2 + f] = f4_to_h4(f4scale(g_dinv[row], xv));
    } else {
        float4 a0 = make_float4(0.f, 0.f, 0.f, 0.f), a1 = a0, a2 = a0, a3 = a0;
        int i = s;
        for (; i + 4 <= e; i += 4) {
            int c0 = __ldg(ec + i), c1 = __ldg(ec + i + 1);
            int c2 = __ldg(ec + i + 2), c3 = __ldg(ec + i + 3);
            a0 = f4add(a0, h4_to_f4(__ldg(src + c0 * HS2 + f)));
            a1 = f4add(a1, h4_to_f4(__ldg(src + c1 * HS2 + f)));
            a2 = f4add(a2, h4_to_f4(__ldg(src + c2 * HS2 + f)));
            a3 = f4add(a3, h4_to_f4(__ldg(src + c3 * HS2 + f)));
        }
        for (; i < e; i++) {
            int c = __ldg(ec + i);
            a0 = f4add(a0, h4_to_f4(__ldg(src + c * HS2 + f)));
        }
        float4 sum = f4add(f4add(a0, a1), f4add(a2, a3));
        float dr = g_dinv[row];
        if (MODE == 0) {
            float4 t1 = f4scale(-dr, sum);
            ((float4*)g_T1)[row * D4 + f] = t1;
            ((uint2*)g_Y2h)[row * HS2 + f] = f4_to_h4(f4scale(dr, t1));
        } else {
            float4 xr = __ldg((const float4*)g_X + row * D4 + f);
            float4 t2;
            float nd = -2.0f * dr;
            t2.x = fmaf(nd, sum.x, -xr.x);
            t2.y = fmaf(nd, sum.y, -xr.y);
            t2.z = fmaf(nd, sum.z, -xr.z);
            t2.w = fmaf(nd, sum.w, -xr.w);
            ((float4*)g_T2)[row * D4 + f] = t2;
        }
    }
}

// ------- fused cheb GEMM + BN stats: Th = relu(X@W0+T1@W1+T2@W2+b) ---------
#define TILE_N 64
#define XS_STRIDE 68

__global__ __launch_bounds__(192) void k_gemm(const float* __restrict__ W,
                                              const float* __restrict__ b,
                                              int NN) {
    __shared__ float xs[144 * XS_STRIDE];
    __shared__ float bsum[48], bsq[48];
    int tid = threadIdx.x;
    int f_id = tid % 12;
    int n_id = tid / 12;
    int f0 = f_id * 4;
    int n0 = n_id * 4;

    if (tid < 48) { bsum[tid] = 0.f; bsq[tid] = 0.f; }

    int nodebase = blockIdx.x * TILE_N;

    for (int v = tid; v < 3 * TILE_N * 12; v += 192) {
        int buf = v / (TILE_N * 12);
        int rem = v % (TILE_N * 12);
        int node = rem / 12;
        int c4 = rem % 12;
        const float* sp = (buf == 0) ? g_X : (buf == 1) ? g_T1 : g_T2;
        float4 val = make_float4(0.f, 0.f, 0.f, 0.f);
        int gn = nodebase + node;
        if (gn < NN) val = *(const float4*)(sp + gn * D + c4 * 4);
        int kb = buf * 48 + c4 * 4;
        xs[(kb + 0) * XS_STRIDE + node] = val.x;
        xs[(kb + 1) * XS_STRIDE + node] = val.y;
        xs[(kb + 2) * XS_STRIDE + node] = val.z;
        xs[(kb + 3) * XS_STRIDE + node] = val.w;
    }
    __syncthreads();

    float acc[4][4];
#pragma unroll
    for (int i = 0; i < 4; i++)
#pragma unroll
        for (int j = 0; j < 4; j++) acc[i][j] = 0.0f;

#pragma unroll 4
    for (int k = 0; k < 144; k++) {
        float4 wv = __ldg((const float4*)(W + k * 48 + f0));
        float4 xv = *(const float4*)&xs[k * XS_STRIDE + n0];
        acc[0][0] = fmaf(xv.x, wv.x, acc[0][0]);
        acc[0][1] = fmaf(xv.x, wv.y, acc[0][1]);
        acc[0][2] = fmaf(xv.x, wv.z, acc[0][2]);
        acc[0][3] = fmaf(xv.x, wv.w, acc[0][3]);
        acc[1][0] = fmaf(xv.y, wv.x, acc[1][0]);
        acc[1][1] = fmaf(xv.y, wv.y, acc[1][1]);
        acc[1][2] = fmaf(xv.y, wv.z, acc[1][2]);
        acc[1][3] = fmaf(xv.y, wv.w, acc[1][3]);
        acc[2][0] = fmaf(xv.z, wv.x, acc[2][0]);
        acc[2][1] = fmaf(xv.z, wv.y, acc[2][1]);
        acc[2][2] = fmaf(xv.z, wv.z, acc[2][2]);
        acc[2][3] = fmaf(xv.z, wv.w, acc[2][3]);
        acc[3][0] = fmaf(xv.w, wv.x, acc[3][0]);
        acc[3][1] = fmaf(xv.w, wv.y, acc[3][1]);
        acc[3][2] = fmaf(xv.w, wv.z, acc[3][2]);
        acc[3][3] = fmaf(xv.w, wv.w, acc[3][3]);
    }

    float4 bv = __ldg((const float4*)(b + f0));
    float4 ps = make_float4(0.f, 0.f, 0.f, 0.f);
    float4 pq = ps;
#pragma unroll
    for (int i = 0; i < 4; i++) {
        int gn = nodebase + n0 + i;
        if (gn < NN) {
            float4 o;
            o.x = fmaxf(acc[i][0] + bv.x, 0.0f);
            o.y = fmaxf(acc[i][1] + bv.y, 0.0f);
            o.z = fmaxf(acc[i][2] + bv.z, 0.0f);
            o.w = fmaxf(acc[i][3] + bv.w, 0.0f);
            ((uint2*)g_Th)[gn * HS2 + f_id] = f4_to_h4(o);
            ps = f4add(ps, o);
            pq.x = fmaf(o.x, o.x, pq.x);
            pq.y = fmaf(o.y, o.y, pq.y);
            pq.z = fmaf(o.z, o.z, pq.z);
            pq.w = fmaf(o.w, o.w, pq.w);
        }
    }
    atomicAdd(&bsum[f0 + 0], ps.x);
    atomicAdd(&bsum[f0 + 1], ps.y);
    atomicAdd(&bsum[f0 + 2], ps.z);
    atomicAdd(&bsum[f0 + 3], ps.w);
    atomicAdd(&bsq[f0 + 0], pq.x);
    atomicAdd(&bsq[f0 + 1], pq.y);
    atomicAdd(&bsq[f0 + 2], pq.z);
    atomicAdd(&bsq[f0 + 3], pq.w);
    __syncthreads();
    if (tid < 48) {
        atomicAdd(&g_bnsum[tid], (double)bsum[tid]);
        atomicAdd(&g_bnsq[tid], (double)bsq[tid]);
    }
}

__global__ void k_bnfin(const float* __restrict__ gamma,
                        const float* __restrict__ beta, int NN) {
    int f = threadIdx.x;
    if (f < D) {
        double mean = g_bnsum[f] / (double)NN;
        double var = g_bnsq[f] / (double)NN - mean * mean;
        float a = gamma[f] * rsqrtf((float)var + BN_EPS);
        g_a[f] = a;
        g_c[f] = beta[f] - (float)mean * a;
        g_bnsum[f] = 0.0;  // reset for next iteration / next replay
        g_bnsq[f] = 0.0;
    }
}

// ---------------- graph boundaries (batch is sorted) ----------------
__global__ void k_gstart(const void* __restrict__ batch, int NN) {
    int is64 = g_is64;
    int i = blockIdx.x * blockDim.x + threadIdx.x;
    if (i > NN) return;
    int bi = (i < NN) ? idx_get(batch, i, is64) : NGRAPH;
    int bp = (i > 0) ? idx_get(batch, i - 1, is64) : -1;
    if (bi < 0) bi = 0;
    if (bi > NGRAPH) bi = NGRAPH;
    if (bp < -1) bp = -1;
    if (bp > NGRAPH) bp = NGRAPH;
    for (int g = bp + 1; g <= bi; g++) g_gstart[g] = i;
}

// ---------------- global add pool: one block per graph ----------------
__global__ __launch_bounds__(240) void k_gsum() {
    __shared__ float sh[5 * D];
    int g = blockIdx.x;
    int t = threadIdx.x;
    int f = t % D;
    int s = t / D;  // 0..4
    int st = g_gstart[g], en = g_gstart[g + 1];
    float acc = 0.0f;
    for (int n = st + s; n < en; n += 5) acc += g_X[n * D + f];
    sh[s * D + f] = acc;
    __syncthreads();
    if (t < D) {
        float v = sh[t] + sh[D + t] + sh[2 * D + t] + sh[3 * D + t] + sh[4 * D + t];
        g_g[g * D + t] = v;
    }
}

// ---------------- final MLP: one block per graph ----------------
__global__ __launch_bounds__(128) void k_mlp(const float* __restrict__ W1,
                                             const float* __restrict__ b1,
                                             const float* __restrict__ W2,
                                             const float* __restrict__ b2,
                                             float* __restrict__ out) {
    __shared__ float gr[D];
    __shared__ float hs[128];
    int g = blockIdx.x;
    int t = threadIdx.x;
    if (t < D) gr[t] = g_g[g * D + t];
    __syncthreads();
    float a = b1[t];
#pragma unroll
    for (int k = 0; k < D; k++) a = fmaf(gr[k], W1[k * 128 + t], a);
    hs[t] = fmaxf(a, 0.0f);
    __syncthreads();
    if (t < 12) {
        float o = b2[t];
#pragma unroll
        for (int j = 0; j < 128; j++) o = fmaf(hs[j], W2[j * 12 + t], o);
        out[g * 12 + t] = o;
    }
}

// ---------------- host orchestration ----------------
extern "C" void kernel_launch(void* const* d_in, const int* in_sizes, int n_in,
                              void* d_out, int out_size) {
    const float* x    = (const float*)d_in[0];
    const void* ei    = d_in[1];
    const void* batch = d_in[2];
    int base = 3;
    if (n_in >= 12 && in_sizes[3] < 100) base = 4;
    const float* W     = (const float*)d_in[base + 0];
    const float* b     = (const float*)d_in[base + 1];
    const float* gamma = (const float*)d_in[base + 2];
    const float* beta  = (const float*)d_in[base + 3];
    const float* W1    = (const float*)d_in[base + 4];
    const float* b1    = (const float*)d_in[base + 5];
    const float* W2    = (const float*)d_in[base + 6];
    const float* b2    = (const float*)d_in[base + 7];

    int NN = in_sizes[0] / D;
    int EE = in_sizes[1] / 2;
    if (NN > NMAX) NN = NMAX;
    if (EE > EMAX) EE = EMAX;

    k_init<<<2048, 256>>>(x, ei, NN, EE);
    k_count<<<2048, 256>>>(ei, EE, NN);
    int NB = (NN + 1023) / 1024;
    k_scan1<<<NB, 1024>>>(NN);                 // scan + dinv + degree hist
    k_scan2<<<1, 128>>>(NB);
    k_scan3<<<NB, 1024>>>(NN, EE);
    k_dscan<<<1, DEGB>>>();                    // degree-bucket offsets
    k_dscatter<<<(NN + 511) / 512, 512>>>(NN); // perm (degree-sorted rows)
    k_bucket<<<2048, 256>>>(ei, EE, NN);
    k_gstart<<<(NN + 256) / 256, 256>>>(batch, NN);
    k_prescale<<<1184, 256>>>(NN);             // Yh = half(dinv*X)

    dim3 gb(12, 32);
    int ggrid = (NN + 31) / 32;
    int gemm_grid = (NN + TILE_N - 1) / TILE_N;

    for (int it = 0; it < NSTEPS; it++) {
        k_gather<0><<<ggrid, gb>>>(NN);        // T1, Y2h
        k_gather<1><<<ggrid, gb>>>(NN);        // T2
        k_gemm<<<gemm_grid, 192>>>(W, b, NN);  // Th = relu(cheb), BN stats
        k_bnfin<<<1, 64>>>(gamma, beta, NN);   // a, c; reset sums
        k_gather<2><<<ggrid, gb>>>(NN);        // X = pool(BN(Th)), Yh
    }

    k_gsum<<<NGRAPH, 240>>>();
    k_mlp<<<NGRAPH, 128>>>(W1, b1, W2, b2, (float*)d_out);
}

// round 8
// speedup vs baseline: 2.4266x; 1.1432x over previous
#include <cuda_runtime.h>
#include <cuda_bf16.h>
#include <cuda_fp16.h>
#include <stdint.h>

#define NMAX 100000
#define EMAX 1600000
#define D 48
#define D4 12
#define HSTRIDE 64   // halfs per row (48 used, padded to 128 B)
#define HS2 16       // uint2 per row
#define NSTEPS 5
#define NGRAPH 64
#define DEGB 512
#define BN_EPS 1e-5f
#define ASTR 148     // smem A stride (uints) for tf32 GEMM

// ---------------- device scratch ----------------
__device__ int   g_deg[NMAX];
__device__ float g_dinv[NMAX];
__device__ int   g_rowstart[NMAX + 1];
__device__ int   g_wp[NMAX];
__device__ int   g_ecol[EMAX];
__device__ int   g_scanblk[256];
__device__ int   g_scanoff[256];
__device__ int   g_dhist[DEGB];
__device__ int   g_doff[DEGB];
__device__ int   g_perm[NMAX];
__device__ unsigned g_Wt[144 * 48];                    // tf32-converted weights
__device__ __align__(16) float  g_X [NMAX * D];
__device__ __align__(16) float  g_T1[NMAX * D];
__device__ __align__(16) float  g_T2[NMAX * D];
__device__ __align__(16) __half g_Yh [NMAX * HSTRIDE];
__device__ __align__(16) __half g_Y2h[NMAX * HSTRIDE];
__device__ __align__(16) __half g_Th [NMAX * HSTRIDE];
__device__ double g_bnsum[D];
__device__ double g_bnsq[D];
__device__ float g_g[NGRAPH * D];
__device__ int   g_gstart[NGRAPH + 1];

// ---------------- helpers ----------------
__device__ __forceinline__ float4 f4add(float4 a, float4 b) {
    return make_float4(a.x + b.x, a.y + b.y, a.z + b.z, a.w + b.w);
}
__device__ __forceinline__ float4 f4max(float4 a, float4 b) {
    return make_float4(fmaxf(a.x, b.x), fmaxf(a.y, b.y), fmaxf(a.z, b.z),
                       fmaxf(a.w, b.w));
}
__device__ __forceinline__ float4 f4fma(float4 a, float4 v, float4 c) {
    return make_float4(fmaf(a.x, v.x, c.x), fmaf(a.y, v.y, c.y),
                       fmaf(a.z, v.z, c.z), fmaf(a.w, v.w, c.w));
}
__device__ __forceinline__ float4 f4scale(float s, float4 v) {
    return make_float4(s * v.x, s * v.y, s * v.z, s * v.w);
}
__device__ __forceinline__ float4 h4_to_f4(uint2 v) {
    __half2 h0 = *(__half2*)&v.x;
    __half2 h1 = *(__half2*)&v.y;
    float2 f0 = __half22float2(h0);
    float2 f1 = __half22float2(h1);
    return make_float4(f0.x, f0.y, f1.x, f1.y);
}
__device__ __forceinline__ uint2 f4_to_h4(float4 f) {
    __half2 h0 = __floats2half2_rn(f.x, f.y);
    __half2 h1 = __floats2half2_rn(f.z, f.w);
    uint2 r;
    r.x = *(unsigned*)&h0;
    r.y = *(unsigned*)&h1;
    return r;
}
__device__ __forceinline__ int idx_get(const void* p, int i, int is64) {
    return is64 ? (int)((const long long*)p)[i] : ((const int*)p)[i];
}
// Inline dtype probe: int64 data looks valid at int64 indices 0..3; int32 data
// fuses index pairs into values >= 2^32 (the hi half is a random node id).
__device__ __forceinline__ int probe64(const void* p, int NN) {
    const long long* q = (const long long*)p;
    long long v0 = q[0], v1 = q[1], v2 = q[2], v3 = q[3];
    return (v0 >= 0 && v0 < NN && v1 >= 0 && v1 < NN && v2 >= 0 && v2 < NN &&
            v3 >= 0 && v3 < NN);
}
__device__ __forceinline__ unsigned f2tf32(float f) {
    unsigned u;
    asm("cvt.rna.tf32.f32 %0, %1;" : "=r"(u) : "f"(f));
    return u;
}

// ------- pre0: copy X, count deg, gstart, convert W, zero bnsums -----------
__global__ void k_pre0(const float* __restrict__ x, const void* ei,
                       const void* batch, const float* __restrict__ W, int NN,
                       int EE) {
    int gt = blockIdx.x * blockDim.x + threadIdx.x;
    int gs = gridDim.x * blockDim.x;
    int is64 = probe64(ei, NN);

    // copy X (deg is zeroed by previous replay's dscatter / BSS init)
    for (int i = gt; i < NN * D4; i += gs)
        ((float4*)g_X)[i] = ((const float4*)x)[i];
    // degree count
    for (int e = gt; e < EE; e += gs) {
        int r = idx_get(ei, e, is64);
        if ((unsigned)r < (unsigned)NN) atomicAdd(&g_deg[r], 1);
    }
    // graph boundaries (batch sorted)
    for (int i = gt; i <= NN; i += gs) {
        int bi = (i < NN) ? idx_get(batch, i, is64) : NGRAPH;
        int bp = (i > 0) ? idx_get(batch, i - 1, is64) : -1;
        if (bi < 0) bi = 0;
        if (bi > NGRAPH) bi = NGRAPH;
        if (bp < -1) bp = -1;
        if (bp > NGRAPH) bp = NGRAPH;
        for (int g = bp + 1; g <= bi; g++) g_gstart[g] = i;
    }
    // tf32 weights
    for (int i = gt; i < 144 * 48; i += gs) g_Wt[i] = f2tf32(W[i]);
    // zero BN sums for first gemm of this replay
    if (gt < D) { g_bnsum[gt] = 0.0; g_bnsq[gt] = 0.0; }
}

// ---------------- prefix scan over deg (+dinv +degree histogram) -----------
__global__ void k_scan1(int NN) {
    __shared__ int sh[1024];
    __shared__ int hist[DEGB];
    int t = threadIdx.x;
    if (t < DEGB) hist[t] = 0;
    int i = blockIdx.x * 1024 + t;
    int v = (i < NN) ? g_deg[i] : 0;
    sh[t] = v;
    __syncthreads();
    for (int off = 1; off < 1024; off <<= 1) {
        int tv = (t >= off) ? sh[t - off] : 0;
        __syncthreads();
        sh[t] += tv;
        __syncthreads();
    }
    if (i < NN) {
        g_rowstart[i] = sh[t] - v;
        g_dinv[i] = (v > 0) ? rsqrtf((float)v) : 0.0f;
        atomicAdd(&hist[v < DEGB ? v : DEGB - 1], 1);
    }
    if (t == 1023) g_scanblk[blockIdx.x] = sh[1023];
    __syncthreads();
    if (t < DEGB && hist[t] > 0) atomicAdd(&g_dhist[t], hist[t]);
}

__global__ void k_scan2(int NB) {
    __shared__ int sh[128];
    int t = threadIdx.x;
    int v = (t < NB) ? g_scanblk[t] : 0;
    sh[t] = v;
    __syncthreads();
    for (int off = 1; off < 128; off <<= 1) {
        int tv = (t >= off) ? sh[t - off] : 0;
        __syncthreads();
        sh[t] += tv;
        __syncthreads();
    }
    g_scanoff[t] = sh[t] - v;
}

// scan3 + prescale (Yh = half(dinv*X)) fused
__global__ void k_scan3(int NN, int EE) {
    int i = blockIdx.x * 1024 + threadIdx.x;
    if (i < NN) {
        int rs = g_rowstart[i] + g_scanoff[blockIdx.x];
        g_rowstart[i] = rs;
        g_wp[i] = rs;
    }
    if (i == 0) g_rowstart[NN] = EE;
    int gs = gridDim.x * 1024;
    for (int v = i; v < NN * D4; v += gs) {
        int row = v / D4, f = v % D4;
        float4 val = f4scale(g_dinv[row], ((const float4*)g_X)[v]);
        ((uint2*)g_Yh)[row * HS2 + f] = f4_to_h4(val);
    }
}

// ---------------- degree counting sort ----------------
__global__ void k_dscan() {
    __shared__ int sh[DEGB];
    int t = threadIdx.x;
    int v = g_dhist[t];
    sh[t] = v;
    __syncthreads();
    for (int off = 1; off < DEGB; off <<= 1) {
        int tv = (t >= off) ? sh[t - off] : 0;
        __syncthreads();
        sh[t] += tv;
        __syncthreads();
    }
    g_doff[t] = sh[t] - v;
    g_dhist[t] = 0;  // reset for next replay
}

__global__ void k_dscatter(int NN) {
    __shared__ int lh[DEGB];
    __shared__ int lbase[DEGB];
    int t = threadIdx.x;
    lh[t] = 0;
    __syncthreads();
    int i = blockIdx.x * 512 + t;
    int d = 0, lr = 0;
    if (i < NN) {
        d = g_deg[i];
        if (d >= DEGB) d = DEGB - 1;
        lr = atomicAdd(&lh[d], 1);
        g_deg[i] = 0;  // reset for next replay
    }
    __syncthreads();
    if (lh[t] > 0) lbase[t] = atomicAdd(&g_doff[t], lh[t]);
    __syncthreads();
    if (i < NN) g_perm[lbase[d] + lr] = i;
}

__global__ void k_bucket(const void* __restrict__ ei, int EE, int NN) {
    int is64 = probe64(ei, NN);
    for (int e = blockIdx.x * blockDim.x + threadIdx.x; e < EE;
         e += gridDim.x * blockDim.x) {
        int r = idx_get(ei, e, is64);
        int c = idx_get(ei, EE + e, is64);
        if ((unsigned)r < (unsigned)NN && (unsigned)c < (unsigned)NN) {
            int p = atomicAdd(&g_wp[r], 1);
            if ((unsigned)p < (unsigned)EMAX) g_ecol[p] = c;
        }
    }
}

// ---------------- CSR gather kernels ----------
// MODE 0: T1 = -dinv*sum(Yh[c]);  Y2h = dinv*T1;  block 0 zeroes BN sums
// MODE 1: T2 = -2*dinv*sum(Y2h[c]) - X
// MODE 2: inline BN-finalize, then X = deg>0 ? max_c(a*Th[c]+c) : 0; Yh=dinv*X
template <int MODE>
__global__ __launch_bounds__(384) void k_gather(const float* __restrict__ gamma,
                                                const float* __restrict__ beta,
                                                int NN) {
    __shared__ __align__(16) float sa[48], sc[48];
    int lt = threadIdx.y * 12 + threadIdx.x;
    if (MODE == 0) {
        if (blockIdx.x == 0 && lt < D) { g_bnsum[lt] = 0.0; g_bnsq[lt] = 0.0; }
    }
    if (MODE == 2) {
        if (lt < D) {
            double mean = g_bnsum[lt] / (double)NN;
            double var = g_bnsq[lt] / (double)NN - mean * mean;
            float a = gamma[lt] * rsqrtf((float)var + BN_EPS);
            sa[lt] = a;
            sc[lt] = beta[lt] - (float)mean * a;
        }
        __syncthreads();
    }
    int vrow = blockIdx.x * 32 + threadIdx.y;
    if (vrow >= NN) return;
    int row = g_perm[vrow];
    int f = threadIdx.x;  // 0..11
    int s = g_rowstart[row];
    int e = g_rowstart[row + 1];
    const uint2* __restrict__ src =
        (MODE == 0) ? (const uint2*)g_Yh
                    : (MODE == 1) ? (const uint2*)g_Y2h : (const uint2*)g_Th;
    const int* __restrict__ ec = g_ecol;

    if (MODE == 2) {
        float4 av = ((const float4*)sa)[f];
        float4 cv = ((const float4*)sc)[f];
        float NI = __int_as_float(0xff800000);
        float4 m0 = make_float4(NI, NI, NI, NI), m1 = m0, m2 = m0, m3 = m0;
        int i = s;
        for (; i + 4 <= e; i += 4) {
            int c0 = __ldg(ec + i), c1 = __ldg(ec + i + 1);
            int c2 = __ldg(ec + i + 2), c3 = __ldg(ec + i + 3);
            float4 v0 = h4_to_f4(__ldg(src + c0 * HS2 + f));
            float4 v1 = h4_to_f4(__ldg(src + c1 * HS2 + f));
            float4 v2 = h4_to_f4(__ldg(src + c2 * HS2 + f));
            float4 v3 = h4_to_f4(__ldg(src + c3 * HS2 + f));
            m0 = f4max(m0, f4fma(av, v0, cv));
            m1 = f4max(m1, f4fma(av, v1, cv));
            m2 = f4max(m2, f4fma(av, v2, cv));
            m3 = f4max(m3, f4fma(av, v3, cv));
        }
        for (; i < e; i++) {
            int c = __ldg(ec + i);
            m0 = f4max(m0, f4fma(av, h4_to_f4(__ldg(src + c * HS2 + f)), cv));
        }
        float4 m = f4max(f4max(m0, m1), f4max(m2, m3));
        float4 xv = (e > s) ? m : make_float4(0.f, 0.f, 0.f, 0.f);
        ((float4*)g_X)[row * D4 + f] = xv;
        ((uint2*)g_Yh)[row * HS2 + f] = f4_to_h4(f4scale(g_dinv[row], xv));
    } else {
        float4 a0 = make_float4(0.f, 0.f, 0.f, 0.f), a1 = a0, a2 = a0, a3 = a0;
        int i = s;
        for (; i + 4 <= e; i += 4) {
            int c0 = __ldg(ec + i), c1 = __ldg(ec + i + 1);
            int c2 = __ldg(ec + i + 2), c3 = __ldg(ec + i + 3);
            a0 = f4add(a0, h4_to_f4(__ldg(src + c0 * HS2 + f)));
            a1 = f4add(a1, h4_to_f4(__ldg(src + c1 * HS2 + f)));
            a2 = f4add(a2, h4_to_f4(__ldg(src + c2 * HS2 + f)));
            a3 = f4add(a3, h4_to_f4(__ldg(src + c3 * HS2 + f)));
        }
        for (; i < e; i++) {
            int c = __ldg(ec + i);
            a0 = f4add(a0, h4_to_f4(__ldg(src + c * HS2 + f)));
        }
        float4 sum = f4add(f4add(a0, a1), f4add(a2, a3));
        float dr = g_dinv[row];
        if (MODE == 0) {
            float4 t1 = f4scale(-dr, sum);
            ((float4*)g_T1)[row * D4 + f] = t1;
            ((uint2*)g_Y2h)[row * HS2 + f] = f4_to_h4(f4scale(dr, t1));
        } else {
            float4 xr = __ldg((const float4*)g_X + row * D4 + f);
            float4 t2;
            float nd = -2.0f * dr;
            t2.x = fmaf(nd, sum.x, -xr.x);
            t2.y = fmaf(nd, sum.y, -xr.y);
            t2.z = fmaf(nd, sum.z, -xr.z);
            t2.w = fmaf(nd, sum.w, -xr.w);
            ((float4*)g_T2)[row * D4 + f] = t2;
        }
    }
}

// ------- tf32 tensor-core cheb GEMM + fused BN stats -----------------------
// Th = relu([X|T1|T2] @ Wcat + b), Wcat = [144,48] (pre-converted g_Wt).
// Tile: 64 nodes x 48 feats, 4 warps (each m16), K=144 (18 mma k-steps).
__global__ __launch_bounds__(128) void k_gemm(const float* __restrict__ b,
                                              int NN) {
    __shared__ unsigned As[64 * ASTR];  // tf32 A tile, node-major
    __shared__ float bsumS[48], bsqS[48];
    int tid = threadIdx.x;
    int w = tid >> 5;
    int lane = tid & 31;
    int g = lane >> 2;   // 0..7
    int t = lane & 3;    // 0..3
    int nodebase = blockIdx.x * 64;

    if (tid < 48) { bsumS[tid] = 0.f; bsqS[tid] = 0.f; }

    // stage A = [X|T1|T2] rows as tf32
    for (int idx = tid; idx < 64 * 36; idx += 128) {
        int node = idx / 36, q = idx % 36;
        int buf = q / 12, c4 = q % 12;
        int gn = nodebase + node;
        float4 v = make_float4(0.f, 0.f, 0.f, 0.f);
        if (gn < NN) {
            const float* sp = (buf == 0) ? g_X : (buf == 1) ? g_T1 : g_T2;
            v = ((const float4*)sp)[gn * D4 + c4];
        }
        int k = buf * 48 + c4 * 4;
        unsigned* dst = &As[node * ASTR + k];
        dst[0] = f2tf32(v.x);
        dst[1] = f2tf32(v.y);
        dst[2] = f2tf32(v.z);
        dst[3] = f2tf32(v.w);
    }
    __syncthreads();

    float acc[6][4];
#pragma unroll
    for (int j = 0; j < 6; j++)
#pragma unroll
        for (int q = 0; q < 4; q++) acc[j][q] = 0.f;

    const unsigned* __restrict__ Wt = g_Wt;
    int r0s = (w * 16 + g) * ASTR;
    int r1s = (w * 16 + g + 8) * ASTR;
#pragma unroll
    for (int s = 0; s < 18; s++) {
        int k0 = s * 8;
        unsigned a0 = As[r0s + k0 + t];
        unsigned a1 = As[r1s + k0 + t];
        unsigned a2 = As[r0s + k0 + t + 4];
        unsigned a3 = As[r1s + k0 + t + 4];
#pragma unroll
        for (int j = 0; j < 6; j++) {
            unsigned b0 = __ldg(&Wt[(k0 + t) * 48 + j * 8 + g]);
            unsigned b1 = __ldg(&Wt[(k0 + t + 4) * 48 + j * 8 + g]);
            asm volatile(
                "mma.sync.aligned.m16n8k8.row.col.f32.tf32.tf32.f32 "
                "{%0,%1,%2,%3}, {%4,%5,%6,%7}, {%8,%9}, {%0,%1,%2,%3};"
                : "+f"(acc[j][0]), "+f"(acc[j][1]), "+f"(acc[j][2]),
                  "+f"(acc[j][3])
                : "r"(a0), "r"(a1), "r"(a2), "r"(a3), "r"(b0), "r"(b1));
        }
    }

    // epilogue: bias + relu + store fp16 + BN partial sums
    int r0 = nodebase + w * 16 + g;
    int r1 = r0 + 8;
    bool v0 = r0 < NN, v1 = r1 < NN;
#pragma unroll
    for (int j = 0; j < 6; j++) {
        int col0 = j * 8 + 2 * t;
        float bb0 = __ldg(b + col0);
        float bb1 = __ldg(b + col0 + 1);
        float o00 = fmaxf(acc[j][0] + bb0, 0.f);  // (r0, col0)
        float o01 = fmaxf(acc[j][1] + bb1, 0.f);  // (r0, col0+1)
        float o10 = fmaxf(acc[j][2] + bb0, 0.f);  // (r1, col0)
        float o11 = fmaxf(acc[j][3] + bb1, 0.f);  // (r1, col0+1)
        if (v0) {
            __half2 h = __floats2half2_rn(o00, o01);
            ((unsigned*)g_Th)[r0 * 32 + j * 4 + t] = *(unsigned*)&h;
        }
        if (v1) {
            __half2 h = __floats2half2_rn(o10, o11);
            ((unsigned*)g_Th)[r1 * 32 + j * 4 + t] = *(unsigned*)&h;
        }
        float s0 = (v0 ? o00 : 0.f) + (v1 ? o10 : 0.f);
        float s1 = (v0 ? o01 : 0.f) + (v1 ? o11 : 0.f);
        float q0 = (v0 ? o00 * o00 : 0.f) + (v1 ? o10 * o10 : 0.f);
        float q1 = (v0 ? o01 * o01 : 0.f) + (v1 ? o11 * o11 : 0.f);
#pragma unroll
        for (int m = 4; m < 32; m <<= 1) {
            s0 += __shfl_xor_sync(0xffffffffu, s0, m);
            s1 += __shfl_xor_sync(0xffffffffu, s1, m);
            q0 += __shfl_xor_sync(0xffffffffu, q0, m);
            q1 += __shfl_xor_sync(0xffffffffu, q1, m);
        }
        if (g == 0) {
            atomicAdd(&bsumS[col0], s0);
            atomicAdd(&bsumS[col0 + 1], s1);
            atomicAdd(&bsqS[col0], q0);
            atomicAdd(&bsqS[col0 + 1], q1);
        }
    }
    __syncthreads();
    if (tid < 48) {
        atomicAdd(&g_bnsum[tid], (double)bsumS[tid]);
        atomicAdd(&g_bnsq[tid], (double)bsqS[tid]);
    }
}

// ---------------- tail: global add pool + MLP, one block per graph ----------
__global__ __launch_bounds__(256) void k_tail(const float* __restrict__ W1,
                                              const float* __restrict__ b1,
                                              const float* __restrict__ W2,
                                              const float* __restrict__ b2,
                                              float* __restrict__ out) {
    __shared__ float sh[5 * D];
    __shared__ float gr[D];
    __shared__ float hs[128];
    int gph = blockIdx.x;
    int t = threadIdx.x;
    int st = g_gstart[gph], en = g_gstart[gph + 1];
    if (t < 240) {
        int f = t % D;
        int s = t / D;  // 0..4
        float acc = 0.0f;
        for (int n = st + s; n < en; n += 5) acc += g_X[n * D + f];
        sh[s * D + f] = acc;
    }
    __syncthreads();
    if (t < D)
        gr[t] = sh[t] + sh[D + t] + sh[2 * D + t] + sh[3 * D + t] + sh[4 * D + t];
    __syncthreads();
    if (t < 128) {
        float a = b1[t];
#pragma unroll
        for (int k = 0; k < D; k++) a = fmaf(gr[k], W1[k * 128 + t], a);
        hs[t] = fmaxf(a, 0.0f);
    }
    __syncthreads();
    if (t < 12) {
        float o = b2[t];
#pragma unroll
        for (int j = 0; j < 128; j++) o = fmaf(hs[j], W2[j * 12 + t], o);
        out[gph * 12 + t] = o;
    }
}

// ---------------- host orchestration ----------------
extern "C" void kernel_launch(void* const* d_in, const int* in_sizes, int n_in,
                              void* d_out, int out_size) {
    const float* x    = (const float*)d_in[0];
    const void* ei    = d_in[1];
    const void* batch = d_in[2];
    int base = 3;
    if (n_in >= 12 && in_sizes[3] < 100) base = 4;
    const float* W     = (const float*)d_in[base + 0];
    const float* b     = (const float*)d_in[base + 1];
    const float* gamma = (const float*)d_in[base + 2];
    const float* beta  = (const float*)d_in[base + 3];
    const float* W1    = (const float*)d_in[base + 4];
    const float* b1    = (const float*)d_in[base + 5];
    const float* W2    = (const float*)d_in[base + 6];
    const float* b2    = (const float*)d_in[base + 7];

    int NN = in_sizes[0] / D;
    int EE = in_sizes[1] / 2;
    if (NN > NMAX) NN = NMAX;
    if (EE > EMAX) EE = EMAX;

    k_pre0<<<2048, 256>>>(x, ei, batch, W, NN, EE);
    int NB = (NN + 1023) / 1024;
    k_scan1<<<NB, 1024>>>(NN);
    k_scan2<<<1, 128>>>(NB);
    k_scan3<<<NB, 1024>>>(NN, EE);
    k_dscan<<<1, DEGB>>>();
    k_dscatter<<<(NN + 511) / 512, 512>>>(NN);
    k_bucket<<<2048, 256>>>(ei, EE, NN);

    dim3 gb(12, 32);
    int ggrid = (NN + 31) / 32;
    int gemm_grid = (NN + 63) / 64;

    for (int it = 0; it < NSTEPS; it++) {
        k_gather<0><<<ggrid, gb>>>(gamma, beta, NN);  // T1, Y2h (+zero sums)
        k_gather<1><<<ggrid, gb>>>(gamma, beta, NN);  // T2
        k_gemm<<<gemm_grid, 128>>>(b, NN);            // Th, BN stats (tf32 mma)
        k_gather<2><<<ggrid, gb>>>(gamma, beta, NN);  // bnfin + pool + Yh
    }

    k_tail<<<NGRAPH, 256>>>(W1, b1, W2, b2, (float*)d_out);
}